// round 2
// baseline (speedup 1.0000x reference)
#include <cuda_runtime.h>
#include <math.h>

// ===================== problem constants =====================
#define NSAMP 4096          // B*S = 32*128
#define KDIM  28224         // 21*21*64
#define LOG_OFF 0           // logits: 4096*96
#define VAL_OFF 393216      // values: 4096
#define HID_OFF 397312      // new_hidden: 32*64

// ===================== device scratch =====================
__device__ float g_feat[(size_t)NSAMP * KDIM];   // 462 MB conv3 output
__device__ float g_ig[NSAMP * 192];              // input-gate projections
__device__ float g_allh[NSAMP * 64];             // GRU hidden states per step

// ===================== smem layout for build_conv (float offsets) =====================
#define SM_GRID 0
#define SM_C1   14400
#define SM_C2   23396
#define SM_W1   39368
#define SM_W2   40904
#define SM_W3   42952
#define SM_B1   51144
#define SM_B2   51160
#define SM_B3   51192
#define SM_ET   51256
#define SM_EU   51268
#define SM_TOTAL 51396      // floats -> 205,584 bytes dynamic smem

// ===================== fused conv stage =====================
template<int OH, int IH, int ISTR, int CIN, int COUT, int OSTR, int TXW, int TM, bool GOUT>
__device__ __forceinline__ void conv2x2(const float* __restrict__ in,
                                        const float* __restrict__ wgt,
                                        const float* __restrict__ bias,
                                        float* __restrict__ out, int tid)
{
    const int NTY = 256 / TXW;
    const int tx = tid % TXW;
    const int ty = tid / TXW;
    const float bv0 = bias[tx*4+0], bv1 = bias[tx*4+1];
    const float bv2 = bias[tx*4+2], bv3 = bias[tx*4+3];
    const int NPIX = OH * OH;
    for (int p0 = ty*TM; p0 < NPIX; p0 += NTY*TM) {
        const float* inb[TM];
        bool valid[TM];
        float acc[TM][4];
        #pragma unroll
        for (int m = 0; m < TM; m++) {
            int p = p0 + m;
            valid[m] = (p < NPIX);
            int pc = valid[m] ? p : 0;
            int h = pc / OH, w = pc % OH;
            inb[m] = in + (h*IH + w)*ISTR;
            acc[m][0] = acc[m][1] = acc[m][2] = acc[m][3] = 0.f;
        }
        #pragma unroll
        for (int tap = 0; tap < 4; tap++) {
            const int ioff = ((tap>>1)*IH + (tap&1))*ISTR;
            const float* wp = wgt + tap*CIN*COUT + tx*4;
            #pragma unroll 8
            for (int ci = 0; ci < CIN; ci++) {
                float4 wv = *(const float4*)(wp + ci*COUT);
                #pragma unroll
                for (int m = 0; m < TM; m++) {
                    float x = inb[m][ioff + ci];
                    acc[m][0] = fmaf(x, wv.x, acc[m][0]);
                    acc[m][1] = fmaf(x, wv.y, acc[m][1]);
                    acc[m][2] = fmaf(x, wv.z, acc[m][2]);
                    acc[m][3] = fmaf(x, wv.w, acc[m][3]);
                }
            }
        }
        #pragma unroll
        for (int m = 0; m < TM; m++) {
            if (!valid[m]) continue;
            int p = p0 + m;
            float o0 = fmaxf(acc[m][0] + bv0, 0.f);
            float o1 = fmaxf(acc[m][1] + bv1, 0.f);
            float o2 = fmaxf(acc[m][2] + bv2, 0.f);
            float o3 = fmaxf(acc[m][3] + bv3, 0.f);
            if (GOUT) {
                *(float4*)(out + (size_t)p*COUT + tx*4) = make_float4(o0, o1, o2, o3);
            } else {
                float* op = out + p*OSTR + tx*4;
                op[0] = o0; op[1] = o1; op[2] = o2; op[3] = o3;
            }
        }
    }
}

// ===================== kernel 1: grid build + conv1..3 =====================
__global__ void __launch_bounds__(256)
build_conv_kernel(const int* __restrict__ positions,
                  const int* __restrict__ units_mask,       // int32 mask!
                  const int* __restrict__ tile_type,
                  const int* __restrict__ relic_pos,
                  const int* __restrict__ relic_mask,       // int32 mask!
                  const float* __restrict__ reward,
                  const float* __restrict__ emb_tile,
                  const float* __restrict__ emb_unit,
                  const float* __restrict__ w1, const float* __restrict__ b1,
                  const float* __restrict__ w2, const float* __restrict__ b2,
                  const float* __restrict__ w3, const float* __restrict__ b3)
{
    extern __shared__ float sm[];
    const int n = blockIdx.x;      // sample = b*128 + s
    const int t = threadIdx.x;

    // stage weights/embeddings into smem
    for (int i = t; i < 1536; i += 256) sm[SM_W1 + i] = w1[i];
    for (int i = t; i < 2048; i += 256) sm[SM_W2 + i] = w2[i];
    for (int i = t; i < 8192; i += 256) sm[SM_W3 + i] = w3[i];
    if (t < 16)  sm[SM_B1 + t] = b1[t];
    if (t < 32)  sm[SM_B2 + t] = b2[t];
    if (t < 64)  sm[SM_B3 + t] = b3[t];
    if (t < 12)  sm[SM_ET + t] = emb_tile[t];
    if (t < 128) sm[SM_EU + t] = emb_unit[t];
    for (int i = t; i < 14400; i += 256) sm[SM_GRID + i] = 0.f;
    __syncthreads();

    // --- build 24x24x24 grid (ch: 0-3 tile_emb, 4-5 counts, 6-21 uemb, 22 relic, 23 reward)
    const float rv = reward[n];
    for (int cell = t; cell < 576; cell += 256) {
        int tt = tile_type[n*576 + cell];
        float* g = &sm[SM_GRID + cell*25];
        g[0] = sm[SM_ET + tt*4 + 0];
        g[1] = sm[SM_ET + tt*4 + 1];
        g[2] = sm[SM_ET + tt*4 + 2];
        g[3] = sm[SM_ET + tt*4 + 3];
        g[23] = rv;
    }
    {   // 32 (team,unit) pairs x 8 embedding dims -> 256 threads
        int pair = t >> 3, e = t & 7;
        if (units_mask[n*32 + pair] != 0) {
            int team = pair >> 4;
            int px = positions[(n*32 + pair)*2 + 0];
            int py = positions[(n*32 + pair)*2 + 1];
            float* g = &sm[SM_GRID + (px*24 + py)*25];
            atomicAdd(&g[6 + team*8 + e], sm[SM_EU + (pair & 15)*8 + e]);
            if (e == 0) atomicAdd(&g[4 + team], 0.0625f);   // 1/MAXU
        }
    }
    if (t < 6 && relic_mask[n*6 + t] != 0) {
        int px = relic_pos[(n*6 + t)*2 + 0];
        int py = relic_pos[(n*6 + t)*2 + 1];
        atomicAdd(&sm[SM_GRID + (px*24 + py)*25 + 22], 1.0f);
    }
    __syncthreads();

    // conv1: 24x24x24 -> 23x23x16
    conv2x2<23, 24, 25, 24, 16, 17,  4, 2, false>(sm + SM_GRID, sm + SM_W1, sm + SM_B1, sm + SM_C1, t);
    __syncthreads();
    // conv2: 23x23x16 -> 22x22x32
    conv2x2<22, 23, 17, 16, 32, 33,  8, 2, false>(sm + SM_C1, sm + SM_W2, sm + SM_B2, sm + SM_C2, t);
    __syncthreads();
    // conv3: 22x22x32 -> 21x21x64, straight to global feat
    conv2x2<21, 22, 33, 32, 64, 64, 16, 4, true >(sm + SM_C2, sm + SM_W3, sm + SM_B3,
                                                  g_feat + (size_t)n*KDIM, t);
}

// ===================== kernel 2: ig = feat @ Wi^T =====================
// M=4096, N=192, K=28224. BM=64, BN=32, BK=16, 128 threads, 4x4 thread tile.
__global__ void __launch_bounds__(128)
gemm_ig_kernel(const float* __restrict__ Wi)
{
    __shared__ float As[2][64][17];
    __shared__ float Bs[2][16][32];
    const int t   = threadIdx.x;
    const int nb  = blockIdx.x;   // 0..5
    const int mb  = blockIdx.y;   // 0..63
    const int txn = t & 7;        // n-tile (4 cols each)
    const int tym = t >> 3;       // m-tile (4 rows each)

    const int arow = t >> 1, acol = (t & 1) * 8;
    const int bn_  = t >> 2, bk   = (t & 3) * 4;
    const float* Ag = g_feat + (size_t)(mb*64 + arow)*KDIM + acol;
    const float* Bg = Wi     + (size_t)(nb*32 + bn_ )*KDIM + bk;

    float4 a0 = *(const float4*)(Ag);
    float4 a1 = *(const float4*)(Ag + 4);
    float4 b0 = *(const float4*)(Bg);
    As[0][arow][acol+0]=a0.x; As[0][arow][acol+1]=a0.y; As[0][arow][acol+2]=a0.z; As[0][arow][acol+3]=a0.w;
    As[0][arow][acol+4]=a1.x; As[0][arow][acol+5]=a1.y; As[0][arow][acol+6]=a1.z; As[0][arow][acol+7]=a1.w;
    Bs[0][bk+0][bn_]=b0.x; Bs[0][bk+1][bn_]=b0.y; Bs[0][bk+2][bn_]=b0.z; Bs[0][bk+3][bn_]=b0.w;
    __syncthreads();

    float acc[4][4] = {};
    const int NT = KDIM / 16;   // 1764
    for (int kt = 0; kt < NT; kt++) {
        int cur = kt & 1;
        if (kt + 1 < NT) {
            const float* Ap = Ag + (kt + 1) * 16;
            a0 = *(const float4*)(Ap);
            a1 = *(const float4*)(Ap + 4);
            b0 = *(const float4*)(Bg + (kt + 1) * 16);
        }
        #pragma unroll
        for (int k = 0; k < 16; k++) {
            float av[4];
            #pragma unroll
            for (int i = 0; i < 4; i++) av[i] = As[cur][tym*4 + i][k];
            float4 bv = *(const float4*)&Bs[cur][k][txn*4];
            #pragma unroll
            for (int i = 0; i < 4; i++) {
                acc[i][0] = fmaf(av[i], bv.x, acc[i][0]);
                acc[i][1] = fmaf(av[i], bv.y, acc[i][1]);
                acc[i][2] = fmaf(av[i], bv.z, acc[i][2]);
                acc[i][3] = fmaf(av[i], bv.w, acc[i][3]);
            }
        }
        if (kt + 1 < NT) {
            int nxt = cur ^ 1;
            As[nxt][arow][acol+0]=a0.x; As[nxt][arow][acol+1]=a0.y; As[nxt][arow][acol+2]=a0.z; As[nxt][arow][acol+3]=a0.w;
            As[nxt][arow][acol+4]=a1.x; As[nxt][arow][acol+5]=a1.y; As[nxt][arow][acol+6]=a1.z; As[nxt][arow][acol+7]=a1.w;
            Bs[nxt][bk+0][bn_]=b0.x; Bs[nxt][bk+1][bn_]=b0.y; Bs[nxt][bk+2][bn_]=b0.z; Bs[nxt][bk+3][bn_]=b0.w;
        }
        __syncthreads();
    }
    #pragma unroll
    for (int i = 0; i < 4; i++) {
        int m = mb*64 + tym*4 + i;
        *(float4*)(g_ig + (size_t)m*192 + nb*32 + txn*4) =
            make_float4(acc[i][0], acc[i][1], acc[i][2], acc[i][3]);
    }
}

// ===================== kernel 3: GRU scan (1 block per batch) =====================
__global__ void __launch_bounds__(192)
gru_kernel(const float* __restrict__ hidden, const float* __restrict__ Wh,
           const float* __restrict__ bi, const float* __restrict__ bn,
           float* __restrict__ d_out)
{
    const int b = blockIdx.x;     // 0..31
    const int j = threadIdx.x;    // 0..191
    __shared__ float h[64];
    __shared__ float g[192];
    __shared__ float hnb[64];

    float whr[64];
    #pragma unroll
    for (int k = 0; k < 64; k++) whr[k] = Wh[j*64 + k];
    const float bij = bi[j];
    const float bnj = (j >= 128) ? bn[j - 128] : 0.f;
    if (j < 64) h[j] = hidden[b*64 + j];
    __syncthreads();

    for (int s = 0; s < 128; s++) {
        float igv = g_ig[(b*128 + s)*192 + j] + bij;
        float acc = 0.f;
        #pragma unroll
        for (int k = 0; k < 64; k++) acc = fmaf(whr[k], h[k], acc);
        if (j < 128) { g[j] = igv + acc; }
        else         { g[j] = igv; hnb[j - 128] = acc + bnj; }
        __syncthreads();
        if (j < 64) {
            float r  = 1.f / (1.f + expf(-g[j]));
            float z  = 1.f / (1.f + expf(-g[64 + j]));
            float nn = tanhf(g[128 + j] + r * hnb[j]);
            float hn = (1.f - z) * nn + z * h[j];
            h[j] = hn;
            g_allh[(b*128 + s)*64 + j] = hn;
        }
        __syncthreads();
    }
    if (j < 64) d_out[HID_OFF + b*64 + j] = h[j];
}

// ===================== kernel 4: actor/critic heads =====================
__global__ void __launch_bounds__(256)
heads_kernel(const float* __restrict__ Wa1, const float* __restrict__ ba1,
             const float* __restrict__ Wa2, const float* __restrict__ ba2,
             const float* __restrict__ Wc1, const float* __restrict__ bc1,
             const float* __restrict__ Wc2, const float* __restrict__ bc2,
             float* __restrict__ d_out)
{
    __shared__ float outs[16][64];
    __shared__ float as_[16][64];
    __shared__ float cs_[16][64];
    const int t = threadIdx.x;
    const int r0 = blockIdx.x * 16;

    #pragma unroll
    for (int q = 0; q < 4; q++) {
        int idx = q*256 + t;
        outs[idx >> 6][idx & 63] = g_allh[(size_t)(r0 + (idx >> 6))*64 + (idx & 63)];
    }
    __syncthreads();

    #pragma unroll
    for (int q = 0; q < 4; q++) {
        int idx = q*256 + t;          // 1024 (row, jj) pairs
        int row = idx >> 6, jj = idx & 63;
        float accA = ba1[jj], accC = bc1[jj];
        #pragma unroll 8
        for (int k = 0; k < 64; k++) {
            float x = outs[row][k];
            accA = fmaf(x, Wa1[k*64 + jj], accA);
            accC = fmaf(x, Wc1[k*64 + jj], accC);
        }
        as_[row][jj] = tanhf(accA);
        cs_[row][jj] = tanhf(accC);
    }
    __syncthreads();

    #pragma unroll
    for (int q = 0; q < 6; q++) {
        int idx = q*256 + t;          // 1536 logit slots
        int row = idx / 96, l = idx % 96;
        float acc = ba2[l];
        #pragma unroll 8
        for (int jj = 0; jj < 64; jj++) acc = fmaf(as_[row][jj], Wa2[jj*96 + l], acc);
        d_out[LOG_OFF + (size_t)(r0 + row)*96 + l] = acc;
    }
    if (t < 16) {
        float acc = bc2[0];
        #pragma unroll 8
        for (int jj = 0; jj < 64; jj++) acc = fmaf(cs_[t][jj], Wc2[jj], acc);
        d_out[VAL_OFF + r0 + t] = acc;
    }
}

// ===================== launcher =====================
extern "C" void kernel_launch(void* const* d_in, const int* in_sizes, int n_in,
                              void* d_out, int out_size)
{
    const int*   positions  = (const int*)  d_in[0];
    const int*   units_mask = (const int*)  d_in[1];    // bool -> int32 in harness
    const int*   tile_type  = (const int*)  d_in[2];
    const int*   relic_pos  = (const int*)  d_in[3];
    const int*   relic_mask = (const int*)  d_in[4];    // bool -> int32 in harness
    const float* reward     = (const float*)d_in[5];
    const float* hidden     = (const float*)d_in[6];
    const float* emb_tile   = (const float*)d_in[7];
    const float* emb_unit   = (const float*)d_in[8];
    const float* w1  = (const float*)d_in[9];
    const float* b1  = (const float*)d_in[10];
    const float* w2  = (const float*)d_in[11];
    const float* b2  = (const float*)d_in[12];
    const float* w3  = (const float*)d_in[13];
    const float* b3  = (const float*)d_in[14];
    const float* Wi  = (const float*)d_in[15];
    const float* Wh  = (const float*)d_in[16];
    const float* bi  = (const float*)d_in[17];
    const float* bn  = (const float*)d_in[18];
    const float* Wa1 = (const float*)d_in[19];
    const float* ba1 = (const float*)d_in[20];
    const float* Wa2 = (const float*)d_in[21];
    const float* ba2 = (const float*)d_in[22];
    const float* Wc1 = (const float*)d_in[23];
    const float* bc1 = (const float*)d_in[24];
    const float* Wc2 = (const float*)d_in[25];
    const float* bc2 = (const float*)d_in[26];
    float* out = (float*)d_out;

    cudaFuncSetAttribute(build_conv_kernel,
                         cudaFuncAttributeMaxDynamicSharedMemorySize, SM_TOTAL * 4);

    build_conv_kernel<<<NSAMP, 256, SM_TOTAL * 4>>>(
        positions, units_mask, tile_type, relic_pos, relic_mask, reward,
        emb_tile, emb_unit, w1, b1, w2, b2, w3, b3);

    dim3 gg(6, 64);
    gemm_ig_kernel<<<gg, 128>>>(Wi);

    gru_kernel<<<32, 192>>>(hidden, Wh, bi, bn, out);

    heads_kernel<<<256, 256>>>(Wa1, ba1, Wa2, ba2, Wc1, bc1, Wc2, bc2, out);
}

// round 4
// speedup vs baseline: 1.5770x; 1.5770x over previous
#include <cuda_runtime.h>
#include <cuda_bf16.h>
#include <math.h>
#include <stdint.h>

// ===================== problem constants =====================
#define NSAMP 4096          // B*S = 32*128
#define KDIM  28224         // 21*21*64
#define KPAD  28672         // padded K
#define KSLICE 14336        // KPAD/2 (per K-part)
#define NCHUNK 224          // KSLICE/64
#define NDIM  192
#define LOG_OFF 0           // logits: 4096*96
#define VAL_OFF 393216      // values: 4096
#define HID_OFF 397312      // new_hidden: 32*64

// ===================== device scratch =====================
// feat in bf16 hi/lo split (pad cols [28224,28672) stay zero: zero-init, never written)
__device__ __nv_bfloat16 g_fhi[(size_t)NSAMP * KPAD];
__device__ __nv_bfloat16 g_flo[(size_t)NSAMP * KPAD];
__device__ __nv_bfloat16 g_wihi[(size_t)NDIM * KPAD];
__device__ __nv_bfloat16 g_wilo[(size_t)NDIM * KPAD];
__device__ float g_igp[(size_t)2 * NSAMP * NDIM];   // K-split partials
__device__ float g_ig[NSAMP * NDIM];
__device__ float g_allh[NSAMP * 64];

// ===================== ptx helpers (base-target only: sm_80+) =====================
__device__ __forceinline__ uint32_t smem_u32(const void* p) {
    uint32_t a;
    asm("{ .reg .u64 t; cvta.to.shared.u64 t, %1; cvt.u32.u64 %0, t; }" : "=r"(a) : "l"(p));
    return a;
}
__device__ __forceinline__ void cp_async16(uint32_t saddr, const void* gaddr) {
    asm volatile("cp.async.cg.shared.global [%0], [%1], 16;" :: "r"(saddr), "l"(gaddr) : "memory");
}
__device__ __forceinline__ void cp_commit() {
    asm volatile("cp.async.commit_group;" ::: "memory");
}
template<int N>
__device__ __forceinline__ void cp_wait() {
    asm volatile("cp.async.wait_group %0;" :: "n"(N) : "memory");
}
__device__ __forceinline__ void ldsm4(uint32_t& r0, uint32_t& r1, uint32_t& r2, uint32_t& r3,
                                      uint32_t addr) {
    asm volatile("ldmatrix.sync.aligned.m8n8.x4.shared.b16 {%0,%1,%2,%3}, [%4];"
                 : "=r"(r0), "=r"(r1), "=r"(r2), "=r"(r3) : "r"(addr));
}
__device__ __forceinline__ void ldsm2(uint32_t& r0, uint32_t& r1, uint32_t addr) {
    asm volatile("ldmatrix.sync.aligned.m8n8.x2.shared.b16 {%0,%1}, [%2];"
                 : "=r"(r0), "=r"(r1) : "r"(addr));
}
__device__ __forceinline__ void mma16816(float* c, const uint32_t* a, const uint32_t* b) {
    asm volatile(
        "mma.sync.aligned.m16n8k16.row.col.f32.bf16.bf16.f32 "
        "{%0,%1,%2,%3}, {%4,%5,%6,%7}, {%8,%9}, {%0,%1,%2,%3};"
        : "+f"(c[0]), "+f"(c[1]), "+f"(c[2]), "+f"(c[3])
        : "r"(a[0]), "r"(a[1]), "r"(a[2]), "r"(a[3]), "r"(b[0]), "r"(b[1]));
}

// ===================== smem layout for build_conv (float offsets) =====================
#define SM_GRID 0
#define SM_C1   14400
#define SM_C2   23396
#define SM_W1   39368
#define SM_W2   40904
#define SM_W3   42952
#define SM_B1   51144
#define SM_B2   51160
#define SM_B3   51192
#define SM_ET   51256
#define SM_EU   51268
#define SM_TOTAL 51396      // floats -> 205,584 bytes dynamic smem

// ===================== fused conv stage =====================
template<int OH, int IH, int ISTR, int CIN, int COUT, int OSTR, int TXW, int TM, bool GOUT>
__device__ __forceinline__ void conv2x2(const float* __restrict__ in,
                                        const float* __restrict__ wgt,
                                        const float* __restrict__ bias,
                                        float* __restrict__ out,
                                        __nv_bfloat16* __restrict__ outHi,
                                        __nv_bfloat16* __restrict__ outLo,
                                        int tid)
{
    const int NTY = 256 / TXW;
    const int tx = tid % TXW;
    const int ty = tid / TXW;
    const float bv0 = bias[tx*4+0], bv1 = bias[tx*4+1];
    const float bv2 = bias[tx*4+2], bv3 = bias[tx*4+3];
    const int NPIX = OH * OH;
    for (int p0 = ty*TM; p0 < NPIX; p0 += NTY*TM) {
        const float* inb[TM];
        bool valid[TM];
        float acc[TM][4];
        #pragma unroll
        for (int m = 0; m < TM; m++) {
            int p = p0 + m;
            valid[m] = (p < NPIX);
            int pc = valid[m] ? p : 0;
            int h = pc / OH, w = pc % OH;
            inb[m] = in + (h*IH + w)*ISTR;
            acc[m][0] = acc[m][1] = acc[m][2] = acc[m][3] = 0.f;
        }
        #pragma unroll
        for (int tap = 0; tap < 4; tap++) {
            const int ioff = ((tap>>1)*IH + (tap&1))*ISTR;
            const float* wp = wgt + tap*CIN*COUT + tx*4;
            #pragma unroll 8
            for (int ci = 0; ci < CIN; ci++) {
                float4 wv = *(const float4*)(wp + ci*COUT);
                #pragma unroll
                for (int m = 0; m < TM; m++) {
                    float x = inb[m][ioff + ci];
                    acc[m][0] = fmaf(x, wv.x, acc[m][0]);
                    acc[m][1] = fmaf(x, wv.y, acc[m][1]);
                    acc[m][2] = fmaf(x, wv.z, acc[m][2]);
                    acc[m][3] = fmaf(x, wv.w, acc[m][3]);
                }
            }
        }
        #pragma unroll
        for (int m = 0; m < TM; m++) {
            if (!valid[m]) continue;
            int p = p0 + m;
            float o0 = fmaxf(acc[m][0] + bv0, 0.f);
            float o1 = fmaxf(acc[m][1] + bv1, 0.f);
            float o2 = fmaxf(acc[m][2] + bv2, 0.f);
            float o3 = fmaxf(acc[m][3] + bv3, 0.f);
            if (GOUT) {
                __nv_bfloat16 h0 = __float2bfloat16(o0);
                __nv_bfloat16 h1 = __float2bfloat16(o1);
                __nv_bfloat16 h2 = __float2bfloat16(o2);
                __nv_bfloat16 h3 = __float2bfloat16(o3);
                __nv_bfloat16 l0 = __float2bfloat16(o0 - __bfloat162float(h0));
                __nv_bfloat16 l1 = __float2bfloat16(o1 - __bfloat162float(h1));
                __nv_bfloat16 l2 = __float2bfloat16(o2 - __bfloat162float(h2));
                __nv_bfloat16 l3 = __float2bfloat16(o3 - __bfloat162float(h3));
                size_t off = (size_t)p*COUT + tx*4;
                __nv_bfloat162 ha; ha.x = h0; ha.y = h1;
                __nv_bfloat162 hb; hb.x = h2; hb.y = h3;
                __nv_bfloat162 la; la.x = l0; la.y = l1;
                __nv_bfloat162 lb; lb.x = l2; lb.y = l3;
                *(__nv_bfloat162*)(outHi + off)     = ha;
                *(__nv_bfloat162*)(outHi + off + 2) = hb;
                *(__nv_bfloat162*)(outLo + off)     = la;
                *(__nv_bfloat162*)(outLo + off + 2) = lb;
            } else {
                float* op = out + p*OSTR + tx*4;
                op[0] = o0; op[1] = o1; op[2] = o2; op[3] = o3;
            }
        }
    }
}

// ===================== kernel 1: grid build + conv1..3 =====================
__global__ void __launch_bounds__(256)
build_conv_kernel(const int* __restrict__ positions,
                  const int* __restrict__ units_mask,
                  const int* __restrict__ tile_type,
                  const int* __restrict__ relic_pos,
                  const int* __restrict__ relic_mask,
                  const float* __restrict__ reward,
                  const float* __restrict__ emb_tile,
                  const float* __restrict__ emb_unit,
                  const float* __restrict__ w1, const float* __restrict__ b1,
                  const float* __restrict__ w2, const float* __restrict__ b2,
                  const float* __restrict__ w3, const float* __restrict__ b3)
{
    extern __shared__ float sm[];
    const int n = blockIdx.x;
    const int t = threadIdx.x;

    for (int i = t; i < 1536; i += 256) sm[SM_W1 + i] = w1[i];
    for (int i = t; i < 2048; i += 256) sm[SM_W2 + i] = w2[i];
    for (int i = t; i < 8192; i += 256) sm[SM_W3 + i] = w3[i];
    if (t < 16)  sm[SM_B1 + t] = b1[t];
    if (t < 32)  sm[SM_B2 + t] = b2[t];
    if (t < 64)  sm[SM_B3 + t] = b3[t];
    if (t < 12)  sm[SM_ET + t] = emb_tile[t];
    if (t < 128) sm[SM_EU + t] = emb_unit[t];
    for (int i = t; i < 14400; i += 256) sm[SM_GRID + i] = 0.f;
    __syncthreads();

    const float rv = reward[n];
    for (int cell = t; cell < 576; cell += 256) {
        int tt = tile_type[n*576 + cell];
        float* g = &sm[SM_GRID + cell*25];
        g[0] = sm[SM_ET + tt*4 + 0];
        g[1] = sm[SM_ET + tt*4 + 1];
        g[2] = sm[SM_ET + tt*4 + 2];
        g[3] = sm[SM_ET + tt*4 + 3];
        g[23] = rv;
    }
    {
        int pair = t >> 3, e = t & 7;
        if (units_mask[n*32 + pair] != 0) {
            int team = pair >> 4;
            int px = positions[(n*32 + pair)*2 + 0];
            int py = positions[(n*32 + pair)*2 + 1];
            float* g = &sm[SM_GRID + (px*24 + py)*25];
            atomicAdd(&g[6 + team*8 + e], sm[SM_EU + (pair & 15)*8 + e]);
            if (e == 0) atomicAdd(&g[4 + team], 0.0625f);
        }
    }
    if (t < 6 && relic_mask[n*6 + t] != 0) {
        int px = relic_pos[(n*6 + t)*2 + 0];
        int py = relic_pos[(n*6 + t)*2 + 1];
        atomicAdd(&sm[SM_GRID + (px*24 + py)*25 + 22], 1.0f);
    }
    __syncthreads();

    conv2x2<23, 24, 25, 24, 16, 17,  4, 2, false>(sm + SM_GRID, sm + SM_W1, sm + SM_B1, sm + SM_C1, 0, 0, t);
    __syncthreads();
    conv2x2<22, 23, 17, 16, 32, 33,  8, 2, false>(sm + SM_C1, sm + SM_W2, sm + SM_B2, sm + SM_C2, 0, 0, t);
    __syncthreads();
    conv2x2<21, 22, 33, 32, 64, 64, 16, 4, true >(sm + SM_C2, sm + SM_W3, sm + SM_B3, 0,
                                                  g_fhi + (size_t)n*KPAD,
                                                  g_flo + (size_t)n*KPAD, t);
}

// ===================== kernel 2a: Wi -> bf16 hi/lo =====================
__global__ void __launch_bounds__(256)
wi_convert_kernel(const float* __restrict__ Wi)
{
    size_t i = (size_t)blockIdx.x * 256 + threadIdx.x;
    if (i >= (size_t)NDIM * KDIM) return;
    int nn = (int)(i / KDIM), k = (int)(i % KDIM);
    float w = Wi[i];
    __nv_bfloat16 h = __float2bfloat16(w);
    __nv_bfloat16 l = __float2bfloat16(w - __bfloat162float(h));
    g_wihi[(size_t)nn*KPAD + k] = h;
    g_wilo[(size_t)nn*KPAD + k] = l;
}

// ===================== kernel 2b: HMMA GEMM ig_partial = feat @ Wi^T =====================
// grid (nb=2, mb=32, kp=2). BM=128, BN=96, BK=64. 8 warps: 2(m) x 4(n), warp tile 64x24.
// 3-pass bf16 hi/lo: Ahi*Bhi + Ahi*Blo + Alo*Bhi, fp32 accum.
// SMEM: padded rows of 72 bf16 (144B stride -> conflict-free ldmatrix).
#define MS_AHI   0
#define MS_ALO   18432      // 128*144
#define MS_BHI   36864
#define MS_BLO   50688      // + 96*144
#define MS_STAGE 64512
#define MS_BYTES (2*64512)  // 129,024 B

__global__ void __launch_bounds__(256)
gemm_mma_kernel()
{
    extern __shared__ char smg[];
    const uint32_t sb = smem_u32(smg);
    const int tid  = threadIdx.x;
    const int wid  = tid >> 5, lane = tid & 31;
    const int nb   = blockIdx.x;          // 0..1
    const int mb   = blockIdx.y;          // 0..31
    const int kp   = blockIdx.z;          // 0..1
    const int wm   = (wid & 1) * 64;      // warp m offset in block
    const int wn   = (wid >> 1) * 24;     // warp n offset in block

    const __nv_bfloat16* Ah = g_fhi  + (size_t)(mb*128)*KPAD + (size_t)kp*KSLICE;
    const __nv_bfloat16* Al = g_flo  + (size_t)(mb*128)*KPAD + (size_t)kp*KSLICE;
    const __nv_bfloat16* Bh = g_wihi + (size_t)(nb*96)*KPAD  + (size_t)kp*KSLICE;
    const __nv_bfloat16* Bl = g_wilo + (size_t)(nb*96)*KPAD  + (size_t)kp*KSLICE;

    // per-thread load indices
    const int lar = tid >> 1, lac = (tid & 1) * 4;   // A: 128 rows x 8 cc (2 rows/thread pattern below)
    (void)lar; (void)lac;

    auto load_stage = [&](int c, int buf) {
        const uint32_t st = sb + buf * MS_STAGE;
        const size_t kof = (size_t)c * 64;
        #pragma unroll
        for (int q = 0; q < 4; q++) {            // A hi/lo: 1024 16B-transfers each
            int idx = tid + q*256;
            int r = idx >> 3, cc = idx & 7;
            uint32_t so = (uint32_t)(r*144 + cc*16);
            const size_t go = (size_t)r*KPAD + kof + cc*8;
            cp_async16(st + MS_AHI + so, Ah + go);
            cp_async16(st + MS_ALO + so, Al + go);
        }
        #pragma unroll
        for (int q = 0; q < 3; q++) {            // B hi/lo: 768 each
            int idx = tid + q*256;
            int r = idx >> 3, cc = idx & 7;
            uint32_t so = (uint32_t)(r*144 + cc*16);
            const size_t go = (size_t)r*KPAD + kof + cc*8;
            cp_async16(st + MS_BHI + so, Bh + go);
            cp_async16(st + MS_BLO + so, Bl + go);
        }
        cp_commit();
    };

    float acc[4][3][4];
    #pragma unroll
    for (int i = 0; i < 4; i++)
        #pragma unroll
        for (int j = 0; j < 3; j++)
            #pragma unroll
            for (int v = 0; v < 4; v++) acc[i][j][v] = 0.f;

    load_stage(0, 0);

    // ldmatrix lane addressing (bytes)
    const uint32_t aRow = (uint32_t)(lane & 15) * 144 + (uint32_t)(lane >> 4) * 16;
    const uint32_t bRow = (uint32_t)(lane & 7) * 144 + (uint32_t)((lane >> 3) & 1) * 16;

    for (int c = 0; c < NCHUNK; c++) {
        const int buf = c & 1;
        if (c + 1 < NCHUNK) { load_stage(c + 1, buf ^ 1); cp_wait<1>(); }
        else                { cp_wait<0>(); }
        __syncthreads();

        const uint32_t st = sb + buf * MS_STAGE;
        #pragma unroll
        for (int ks = 0; ks < 4; ks++) {
            const uint32_t kb = (uint32_t)ks * 32;  // 16 bf16 = 32B
            uint32_t ah[4][4], al[4][4], bh[3][2], bl[3][2];
            #pragma unroll
            for (int mt = 0; mt < 4; mt++) {
                uint32_t ra = st + (uint32_t)(wm + mt*16) * 144 + aRow + kb;
                ldsm4(ah[mt][0], ah[mt][1], ah[mt][2], ah[mt][3], ra + MS_AHI);
                ldsm4(al[mt][0], al[mt][1], al[mt][2], al[mt][3], ra + MS_ALO);
            }
            #pragma unroll
            for (int nt = 0; nt < 3; nt++) {
                uint32_t rb = st + (uint32_t)(wn + nt*8) * 144 + bRow + kb;
                ldsm2(bh[nt][0], bh[nt][1], rb + MS_BHI);
                ldsm2(bl[nt][0], bl[nt][1], rb + MS_BLO);
            }
            #pragma unroll
            for (int mt = 0; mt < 4; mt++)
                #pragma unroll
                for (int nt = 0; nt < 3; nt++) {
                    mma16816(acc[mt][nt], ah[mt], bh[nt]);
                    mma16816(acc[mt][nt], ah[mt], bl[nt]);
                    mma16816(acc[mt][nt], al[mt], bh[nt]);
                }
        }
        __syncthreads();
    }

    // epilogue: C frag -> g_igp[kp]
    const int rbase = mb*128 + wm + (lane >> 2);
    const int cbase = nb*96 + wn + (lane & 3) * 2;
    #pragma unroll
    for (int mt = 0; mt < 4; mt++)
        #pragma unroll
        for (int nt = 0; nt < 3; nt++) {
            int rr = rbase + mt*16;
            int cc = cbase + nt*8;
            float* d0 = g_igp + ((size_t)kp*NSAMP + rr)     * NDIM + cc;
            float* d1 = g_igp + ((size_t)kp*NSAMP + rr + 8) * NDIM + cc;
            *(float2*)d0 = make_float2(acc[mt][nt][0], acc[mt][nt][1]);
            *(float2*)d1 = make_float2(acc[mt][nt][2], acc[mt][nt][3]);
        }
}

// ===================== kernel 2c: reduce partials =====================
__global__ void __launch_bounds__(256)
reduce_ig_kernel()
{
    const size_t NT = (size_t)NSAMP * NDIM;
    size_t i = (size_t)blockIdx.x * 256 + threadIdx.x;
    if (i < NT) g_ig[i] = g_igp[i] + g_igp[NT + i];
}

// ===================== kernel 3: GRU scan (1 block per batch) =====================
__global__ void __launch_bounds__(192)
gru_kernel(const float* __restrict__ hidden, const float* __restrict__ Wh,
           const float* __restrict__ bi, const float* __restrict__ bn,
           float* __restrict__ d_out)
{
    const int b = blockIdx.x;
    const int j = threadIdx.x;
    __shared__ float h[64];
    __shared__ float g[192];
    __shared__ float hnb[64];

    float whr[64];
    #pragma unroll
    for (int k = 0; k < 64; k++) whr[k] = Wh[j*64 + k];
    const float bij = bi[j];
    const float bnj = (j >= 128) ? bn[j - 128] : 0.f;
    if (j < 64) h[j] = hidden[b*64 + j];
    __syncthreads();

    for (int s = 0; s < 128; s++) {
        float igv = g_ig[(b*128 + s)*192 + j] + bij;
        float acc = 0.f;
        #pragma unroll
        for (int k = 0; k < 64; k++) acc = fmaf(whr[k], h[k], acc);
        if (j < 128) { g[j] = igv + acc; }
        else         { g[j] = igv; hnb[j - 128] = acc + bnj; }
        __syncthreads();
        if (j < 64) {
            float r  = 1.f / (1.f + expf(-g[j]));
            float z  = 1.f / (1.f + expf(-g[64 + j]));
            float nn = tanhf(g[128 + j] + r * hnb[j]);
            float hn = (1.f - z) * nn + z * h[j];
            h[j] = hn;
            g_allh[(b*128 + s)*64 + j] = hn;
        }
        __syncthreads();
    }
    if (j < 64) d_out[HID_OFF + b*64 + j] = h[j];
}

// ===================== kernel 4: actor/critic heads =====================
__global__ void __launch_bounds__(256)
heads_kernel(const float* __restrict__ Wa1, const float* __restrict__ ba1,
             const float* __restrict__ Wa2, const float* __restrict__ ba2,
             const float* __restrict__ Wc1, const float* __restrict__ bc1,
             const float* __restrict__ Wc2, const float* __restrict__ bc2,
             float* __restrict__ d_out)
{
    __shared__ float outs[16][64];
    __shared__ float as_[16][64];
    __shared__ float cs_[16][64];
    const int t = threadIdx.x;
    const int r0 = blockIdx.x * 16;

    #pragma unroll
    for (int q = 0; q < 4; q++) {
        int idx = q*256 + t;
        outs[idx >> 6][idx & 63] = g_allh[(size_t)(r0 + (idx >> 6))*64 + (idx & 63)];
    }
    __syncthreads();

    #pragma unroll
    for (int q = 0; q < 4; q++) {
        int idx = q*256 + t;
        int row = idx >> 6, jj = idx & 63;
        float accA = ba1[jj], accC = bc1[jj];
        #pragma unroll 8
        for (int k = 0; k < 64; k++) {
            float x = outs[row][k];
            accA = fmaf(x, Wa1[k*64 + jj], accA);
            accC = fmaf(x, Wc1[k*64 + jj], accC);
        }
        as_[row][jj] = tanhf(accA);
        cs_[row][jj] = tanhf(accC);
    }
    __syncthreads();

    #pragma unroll
    for (int q = 0; q < 6; q++) {
        int idx = q*256 + t;
        int row = idx / 96, l = idx % 96;
        float acc = ba2[l];
        #pragma unroll 8
        for (int jj = 0; jj < 64; jj++) acc = fmaf(as_[row][jj], Wa2[jj*96 + l], acc);
        d_out[LOG_OFF + (size_t)(r0 + row)*96 + l] = acc;
    }
    if (t < 16) {
        float acc = bc2[0];
        #pragma unroll 8
        for (int jj = 0; jj < 64; jj++) acc = fmaf(cs_[t][jj], Wc2[jj], acc);
        d_out[VAL_OFF + r0 + t] = acc;
    }
}

// ===================== launcher =====================
extern "C" void kernel_launch(void* const* d_in, const int* in_sizes, int n_in,
                              void* d_out, int out_size)
{
    const int*   positions  = (const int*)  d_in[0];
    const int*   units_mask = (const int*)  d_in[1];
    const int*   tile_type  = (const int*)  d_in[2];
    const int*   relic_pos  = (const int*)  d_in[3];
    const int*   relic_mask = (const int*)  d_in[4];
    const float* reward     = (const float*)d_in[5];
    const float* hidden     = (const float*)d_in[6];
    const float* emb_tile   = (const float*)d_in[7];
    const float* emb_unit   = (const float*)d_in[8];
    const float* w1  = (const float*)d_in[9];
    const float* b1  = (const float*)d_in[10];
    const float* w2  = (const float*)d_in[11];
    const float* b2  = (const float*)d_in[12];
    const float* w3  = (const float*)d_in[13];
    const float* b3  = (const float*)d_in[14];
    const float* Wi  = (const float*)d_in[15];
    const float* Wh  = (const float*)d_in[16];
    const float* bi  = (const float*)d_in[17];
    const float* bn  = (const float*)d_in[18];
    const float* Wa1 = (const float*)d_in[19];
    const float* ba1 = (const float*)d_in[20];
    const float* Wa2 = (const float*)d_in[21];
    const float* ba2 = (const float*)d_in[22];
    const float* Wc1 = (const float*)d_in[23];
    const float* bc1 = (const float*)d_in[24];
    const float* Wc2 = (const float*)d_in[25];
    const float* bc2 = (const float*)d_in[26];
    float* out = (float*)d_out;

    cudaFuncSetAttribute(build_conv_kernel,
                         cudaFuncAttributeMaxDynamicSharedMemorySize, SM_TOTAL * 4);
    cudaFuncSetAttribute(gemm_mma_kernel,
                         cudaFuncAttributeMaxDynamicSharedMemorySize, MS_BYTES);

    wi_convert_kernel<<<(NDIM*KDIM + 255)/256, 256>>>(Wi);

    build_conv_kernel<<<NSAMP, 256, SM_TOTAL * 4>>>(
        positions, units_mask, tile_type, relic_pos, relic_mask, reward,
        emb_tile, emb_unit, w1, b1, w2, b2, w3, b3);

    dim3 gg(2, 32, 2);
    gemm_mma_kernel<<<gg, 256, MS_BYTES>>>();

    reduce_ig_kernel<<<(NSAMP*NDIM + 255)/256, 256>>>();

    gru_kernel<<<32, 192>>>(hidden, Wh, bi, bn, out);

    heads_kernel<<<256, 256>>>(Wa1, ba1, Wa2, ba2, Wc1, bc1, Wc2, bc2, out);
}